// round 15
// baseline (speedup 1.0000x reference)
#include <cuda_runtime.h>
#include <cuda_fp16.h>
#include <cstdint>

#define BB    4
#define SS    2048
#define DD    1024
#define HH    16
#define DEPTH 64
#define MTOT  (BB * SS)
#define NTK   (SS / 128)

#define MODE_OUT 0
#define MODE_KV  1
#define MODE_Q   2

__device__ uint16_t g_qh [(size_t)BB * HH * SS * DEPTH];
__device__ uint16_t g_kh [(size_t)BB * HH * SS * DEPTH];
__device__ uint16_t g_vh [(size_t)BB * HH * SS * DEPTH];
__device__ uint16_t g_ctxh[(size_t)MTOT * DD];
__device__ uint16_t g_xh [3][(size_t)MTOT * DD];
__device__ uint16_t g_wh [4][(size_t)DD * DD];
__device__ uint16_t g_eh [(size_t)BB * HH * SS * SS];   // fp16 exp scratch
__device__ float    g_attn_fb[(size_t)BB * HH * SS * SS];
__device__ float    g_psum[(size_t)BB * HH * SS * NTK];

// ---------------------------------------------------------------------------
__device__ __forceinline__ uint32_t h2pack(float lo, float hi) {
    __half2 h = __floats2half2_rn(lo, hi);
    return *reinterpret_cast<uint32_t*>(&h);
}

__device__ __forceinline__ void mma_f16(float* c, const uint32_t* a, const uint32_t* b) {
    asm volatile(
        "mma.sync.aligned.m16n8k16.row.col.f32.f16.f16.f32 "
        "{%0,%1,%2,%3}, {%4,%5,%6,%7}, {%8,%9}, {%0,%1,%2,%3};"
        : "+f"(c[0]), "+f"(c[1]), "+f"(c[2]), "+f"(c[3])
        : "r"(a[0]), "r"(a[1]), "r"(a[2]), "r"(a[3]), "r"(b[0]), "r"(b[1]));
}

__device__ __forceinline__ uint32_t smem_u32(const void* p) {
    return (uint32_t)__cvta_generic_to_shared(p);
}

__device__ __forceinline__ void cp16(uint32_t dst, const void* src) {
    asm volatile("cp.async.cg.shared.global [%0], [%1], 16;\n" :: "r"(dst), "l"(src));
}
#define CP_COMMIT() asm volatile("cp.async.commit_group;\n")
#define CP_WAIT(N)  asm volatile("cp.async.wait_group %0;\n" :: "n"(N))

__device__ __forceinline__ void ldsm_x4(uint32_t& r0, uint32_t& r1,
                                        uint32_t& r2, uint32_t& r3, uint32_t addr) {
    asm volatile("ldmatrix.sync.aligned.m8n8.x4.shared.b16 {%0,%1,%2,%3}, [%4];"
                 : "=r"(r0), "=r"(r1), "=r"(r2), "=r"(r3) : "r"(addr));
}

__device__ __forceinline__ void ldsm_x4_trans(uint32_t& r0, uint32_t& r1,
                                              uint32_t& r2, uint32_t& r3, uint32_t addr) {
    asm volatile("ldmatrix.sync.aligned.m8n8.x4.trans.shared.b16 {%0,%1,%2,%3}, [%4];"
                 : "=r"(r0), "=r"(r1), "=r"(r2), "=r"(r3) : "r"(addr));
}

#define TROW 12
#define TROWB (TROW * 4)
#define TBUF (128 * TROW * 4)

// ---------------------------------------------------------------------------
// fp32 -> fp16 conversion
// ---------------------------------------------------------------------------
__global__ __launch_bounds__(256) void to_half_x(
    const float4* __restrict__ q, const float4* __restrict__ k,
    const float4* __restrict__ v, uint16_t* __restrict__ outbase, int n4)
{
    const int z = blockIdx.y;
    const float4* in = (z == 0) ? q : (z == 1) ? k : v;
    uint2* out = (uint2*)(outbase + (size_t)z * MTOT * DD);
    int i = blockIdx.x * blockDim.x + threadIdx.x;
    const int stride = gridDim.x * blockDim.x;
    for (; i < n4; i += stride) {
        float4 w = in[i];
        out[i] = make_uint2(h2pack(w.x, w.y), h2pack(w.z, w.w));
    }
}

__global__ __launch_bounds__(256) void to_half_w(
    const float4* __restrict__ w0, const float4* __restrict__ w1,
    const float4* __restrict__ w2, const float4* __restrict__ w3,
    uint16_t* __restrict__ outbase, int n4)
{
    const int z = blockIdx.y;
    const float4* in = (z == 0) ? w0 : (z == 1) ? w1 : (z == 2) ? w2 : w3;
    uint2* out = (uint2*)(outbase + (size_t)z * DD * DD);
    int i = blockIdx.x * blockDim.x + threadIdx.x;
    const int stride = gridDim.x * blockDim.x;
    for (; i < n4; i += stride) {
        float4 w = in[i];
        out[i] = make_uint2(h2pack(w.x, w.y), h2pack(w.z, w.w));
    }
}

// ---------------------------------------------------------------------------
// Projection core: 128 thr, 128x128, warp 64x64, BK=16, 4-stage cp.async,
// ldmatrix fragments, single barrier per slab.
// ---------------------------------------------------------------------------
__device__ __forceinline__ void proj_body(
    const uint16_t* __restrict__ A, const uint16_t* __restrict__ W,
    const float* __restrict__ bias, void* __restrict__ Cout, int mode,
    uint32_t* dyn)
{
    uint32_t (*As)[128][TROW] = (uint32_t (*)[128][TROW])dyn;
    uint32_t (*Bs)[128][TROW] = (uint32_t (*)[128][TROW])(dyn + 4 * 128 * TROW);

    const int t   = threadIdx.x;
    const int m0  = blockIdx.y * 128;
    const int n0  = blockIdx.x * 128;
    const int wid = t >> 5, lane = t & 31;
    const int wm  = (wid >> 1) * 64;
    const int wn  = (wid & 1) * 64;
    const int g   = lane >> 2, tg = lane & 3;

    const uint16_t* Abase = A + (size_t)m0 * DD;
    const uint16_t* Wbase = W + (size_t)n0 * DD;

    const int lr = lane & 7;
    const uint32_t aoff = (uint32_t)(wm + ((lane >> 3) & 1) * 8 + lr) * TROWB
                        + ((lane >> 4) & 1) * 16;
    const uint32_t boff = (uint32_t)(wn + ((lane >> 4) & 1) * 8 + lr) * TROWB
                        + ((lane >> 3) & 1) * 16;
    const uint32_t asbase = smem_u32(&As[0][0][0]);
    const uint32_t bsbase = smem_u32(&Bs[0][0][0]);

    float acc[4][8][4];
#pragma unroll
    for (int i = 0; i < 4; i++)
#pragma unroll
        for (int j = 0; j < 8; j++)
#pragma unroll
            for (int r = 0; r < 4; r++) acc[i][j][r] = 0.f;

    const int NST = DD / 16;

    auto issue = [&](int p) {
        const int buf = p & 3;
#pragma unroll
        for (int u = 0; u < 2; u++) {
            const int slot = u * 128 + t;
            const int row  = slot >> 1;
            const int q    = slot & 1;
            cp16(smem_u32(&As[buf][row][q * 4]),
                 Abase + (size_t)row * DD + p * 16 + q * 8);
            cp16(smem_u32(&Bs[buf][row][q * 4]),
                 Wbase + (size_t)row * DD + p * 16 + q * 8);
        }
        CP_COMMIT();
    };

    issue(0); issue(1); issue(2);

    for (int s = 0; s < NST; s++) {
        if (s < NST - 2)      { CP_WAIT(2); }
        else if (s == NST - 2){ CP_WAIT(1); }
        else                  { CP_WAIT(0); }
        __syncthreads();
        if (s + 3 < NST) issue(s + 3);

        const int buf = s & 3;
        const uint32_t ab = asbase + (uint32_t)buf * TBUF;
        const uint32_t bb = bsbase + (uint32_t)buf * TBUF;
        uint32_t a[4][4], b[8][2];
#pragma unroll
        for (int i = 0; i < 4; i++)
            ldsm_x4(a[i][0], a[i][1], a[i][2], a[i][3],
                    ab + aoff + (uint32_t)(i * 16) * TROWB);
#pragma unroll
        for (int jj = 0; jj < 4; jj++)
            ldsm_x4(b[2 * jj][0], b[2 * jj][1], b[2 * jj + 1][0], b[2 * jj + 1][1],
                    bb + boff + (uint32_t)(jj * 16) * TROWB);
#pragma unroll
        for (int i = 0; i < 4; i++)
#pragma unroll
            for (int j = 0; j < 8; j++)
                mma_f16(acc[i][j], a[i], b[j]);
    }

#pragma unroll
    for (int i = 0; i < 4; i++) {
#pragma unroll
        for (int j = 0; j < 8; j++) {
            const int n = n0 + wn + j * 8 + 2 * tg;
#pragma unroll
            for (int half = 0; half < 2; half++) {
                const int m = m0 + wm + i * 16 + g + half * 8;
                float v0 = acc[i][j][half * 2 + 0] + bias[n];
                float v1 = acc[i][j][half * 2 + 1] + bias[n + 1];
                if (mode == MODE_OUT) {
                    float* C = (float*)Cout;
                    C[(size_t)m * DD + n]     = v0;
                    C[(size_t)m * DD + n + 1] = v1;
                } else {
                    if (mode == MODE_Q) { v0 *= 0.125f; v1 *= 0.125f; }
                    uint16_t* C = (uint16_t*)Cout;
                    const int bb2 = m / SS, s_ = m % SS;
                    const int h0 = n / DEPTH, d0 = n % DEPTH;
                    *(uint32_t*)&C[(((size_t)(bb2 * HH + h0)) * SS + s_) * DEPTH + d0] =
                        h2pack(v0, v1);
                }
            }
        }
    }
}

__global__ __launch_bounds__(128, 2) void proj_qkv(
    const uint16_t* __restrict__ X, const uint16_t* __restrict__ Wh,
    const float* __restrict__ bq, const float* __restrict__ bk,
    const float* __restrict__ bv,
    uint16_t* __restrict__ Oq, uint16_t* __restrict__ Ok, uint16_t* __restrict__ Ov)
{
    extern __shared__ uint32_t dyn[];
    const int z = blockIdx.z;
    const uint16_t* A = X + (size_t)z * MTOT * DD;
    const uint16_t* W = Wh + (size_t)z * DD * DD;
    const float* bias = (z == 0) ? bq : (z == 1) ? bk : bv;
    uint16_t* O = (z == 0) ? Oq : (z == 1) ? Ok : Ov;
    proj_body(A, W, bias, O, (z == 0) ? MODE_Q : MODE_KV, dyn);
}

__global__ __launch_bounds__(128, 2) void proj_out(
    const uint16_t* __restrict__ A, const uint16_t* __restrict__ W,
    const float* __restrict__ bias, float* __restrict__ C)
{
    extern __shared__ uint32_t dyn[];
    proj_body(A, W, bias, C, MODE_OUT, dyn);
}

// ---------------------------------------------------------------------------
// logits: e = (k<=q) ? exp(Q.K) : 0, fp16 scratch + psums. Masked tiles are
// now entirely handled by ctx (zeros) — masked blocks exit immediately.
// ---------------------------------------------------------------------------
__global__ __launch_bounds__(256) void attn_logits_exp(
    const uint16_t* __restrict__ Qh, const uint16_t* __restrict__ Kh,
    uint16_t* __restrict__ eh, float* __restrict__ psum)
{
    const int bh = blockIdx.z;
    const int tq = blockIdx.y;
    const int tk = blockIdx.x;
    if (tk > tq) return;
    const int t  = threadIdx.x;

    const size_t abase = ((size_t)bh * SS + (size_t)tq * 128) * SS + (size_t)tk * 128;
    float* psrow = psum + ((size_t)bh * SS + (size_t)tq * 128) * NTK + tk;

    __shared__ uint32_t Qs[128][36];
    __shared__ uint32_t Ks[128][36];
    __shared__ float ps_s[128][5];

    const uint16_t* Qb = Qh + ((size_t)bh * SS + (size_t)tq * 128) * DEPTH;
    const uint16_t* Kb = Kh + ((size_t)bh * SS + (size_t)tk * 128) * DEPTH;

    const int wid = t >> 5, lane = t & 31;
    const int wm  = (wid >> 2) * 64;
    const int wn  = (wid & 3) * 32;
    const int g   = lane >> 2, tg = lane & 3;

#pragma unroll
    for (int u = 0; u < 4; u++) {
        const int slot = u * 256 + t;
        const int row  = slot >> 3;
        const int q    = slot & 7;
        cp16(smem_u32(&Qs[row][q * 4]), Qb + (size_t)row * DEPTH + q * 8);
        cp16(smem_u32(&Ks[row][q * 4]), Kb + (size_t)row * DEPTH + q * 8);
    }
    CP_COMMIT();

    float acc[4][4][4];
#pragma unroll
    for (int i = 0; i < 4; i++)
#pragma unroll
        for (int j = 0; j < 4; j++)
#pragma unroll
            for (int r = 0; r < 4; r++) acc[i][j][r] = 0.f;

    CP_WAIT(0);
    __syncthreads();

#pragma unroll
    for (int s = 0; s < 4; s++) {
        const int w0 = s * 8;
        uint32_t a[4][4], b[4][2];
#pragma unroll
        for (int i = 0; i < 4; i++) {
            const int r = wm + i * 16;
            a[i][0] = Qs[r + g][w0 + tg];
            a[i][1] = Qs[r + g + 8][w0 + tg];
            a[i][2] = Qs[r + g][w0 + tg + 4];
            a[i][3] = Qs[r + g + 8][w0 + tg + 4];
        }
#pragma unroll
        for (int j = 0; j < 4; j++) {
            const int n = wn + j * 8;
            b[j][0] = Ks[n + g][w0 + tg];
            b[j][1] = Ks[n + g][w0 + tg + 4];
        }
#pragma unroll
        for (int i = 0; i < 4; i++)
#pragma unroll
            for (int j = 0; j < 4; j++)
                mma_f16(acc[i][j], a[i], b[j]);
    }

    const int qg0 = tq * 128, kg0 = tk * 128;
    float rowacc[4][2];
#pragma unroll
    for (int i = 0; i < 4; i++) { rowacc[i][0] = 0.f; rowacc[i][1] = 0.f; }

#pragma unroll
    for (int i = 0; i < 4; i++) {
#pragma unroll
        for (int j = 0; j < 4; j++) {
            const int kn = wn + j * 8 + 2 * tg;
#pragma unroll
            for (int half = 0; half < 2; half++) {
                const int qm = wm + i * 16 + g + half * 8;
                const int qg = qg0 + qm;
                const float v0 = (kg0 + kn     <= qg) ? __expf(acc[i][j][half * 2 + 0]) : 0.f;
                const float v1 = (kg0 + kn + 1 <= qg) ? __expf(acc[i][j][half * 2 + 1]) : 0.f;
                const uint32_t pair = h2pack(v0, v1);
                *(uint32_t*)&eh[abase + (size_t)qm * SS + kn] = pair;
                float2 fr = __half22float2(*(const __half2*)&pair);
                rowacc[i][half] += fr.x + fr.y;
            }
        }
    }
#pragma unroll
    for (int i = 0; i < 4; i++)
#pragma unroll
        for (int half = 0; half < 2; half++) {
            float v = rowacc[i][half];
            v += __shfl_xor_sync(0xffffffffu, v, 1);
            v += __shfl_xor_sync(0xffffffffu, v, 2);
            if (tg == 0) ps_s[wm + i * 16 + g + half * 8][wid & 3] = v;
        }
    __syncthreads();
    if (t < 128) {
        const float s4 = (ps_s[t][0] + ps_s[t][1]) + (ps_s[t][2] + ps_s[t][3]);
        psrow[(size_t)t * NTK] = s4;
    }
}

// ---------------------------------------------------------------------------
// ctx: acc = sum_k e·V, epilogue scale by inv; emits normalized fp32 attn
// AND fills its rows' masked attn columns with zeros (overlaps with mma).
// inv sums only the tq+1 valid psum entries. Longest-first schedule.
// ---------------------------------------------------------------------------
__global__ __launch_bounds__(128, 2) void attn_ctx_f16(
    const uint16_t* __restrict__ eh, const uint16_t* __restrict__ Vh,
    const float* __restrict__ psum, float* __restrict__ attn,
    uint16_t* __restrict__ ctx)
{
    const int tq = (NTK - 1) - blockIdx.x;
    const int bh = blockIdx.y;
    const int bb = bh / HH, h = bh % HH;
    const int t  = threadIdx.x;

    __shared__ uint32_t As[2][128][TROW];
    __shared__ uint32_t Vs[2][16][36];
    __shared__ float inv_s[128];

    const size_t qrow0 = (size_t)bh * SS + (size_t)tq * 128;
    const uint16_t* Eb = eh + qrow0 * SS;
    const uint16_t* Vb = Vh + (size_t)bh * SS * DEPTH;
    float* Ab = attn + qrow0 * SS;

    const int wid = t >> 5, lane = t & 31;
    const int wm  = (wid >> 1) * 64;
    const int wn  = (wid & 1) * 32;
    const int g   = lane >> 2, tg = lane & 3;

    const int lr = lane & 7;
    const uint32_t aoff = (uint32_t)(wm + ((lane >> 3) & 1) * 8 + lr) * TROWB
                        + ((lane >> 4) & 1) * 16;
    const uint32_t asbase = smem_u32(&As[0][0][0]);

    const uint32_t vbase[2] = { smem_u32(&Vs[0][0][0]), smem_u32(&Vs[1][0][0]) };
    uint32_t voff[2];
#pragma unroll
    for (int p = 0; p < 2; p++) {
        const int n0 = wn + p * 16 + (lane >> 4) * 8;
        voff[p] = (uint32_t)(((lane & 15) * 36 + (n0 >> 1)) * 4);
    }

    // inv from the tq+1 valid psum entries only
    {
        const float* p0 = psum + (qrow0 + t) * NTK;
        float s0 = 0.f;
        for (int u = 0; u <= tq; u++) s0 += p0[u];
        inv_s[t] = 1.0f / s0;
    }

    float acc[4][4][4];
#pragma unroll
    for (int i = 0; i < 4; i++)
#pragma unroll
        for (int j = 0; j < 4; j++)
#pragma unroll
            for (int r = 0; r < 4; r++) acc[i][j][r] = 0.f;

    const int NST = (tq + 1) * 8;

    const int ar0 = t >> 1,          aq0 = (t & 1);
    const int ar1 = (t + 128) >> 1,  aq1 = ((t + 128) & 1);

    auto issue = [&](int s) {
        const int buf = s & 1;
        cp16(smem_u32(&As[buf][ar0][aq0 * 4]),
             Eb + (size_t)ar0 * SS + s * 16 + aq0 * 8);
        cp16(smem_u32(&As[buf][ar1][aq1 * 4]),
             Eb + (size_t)ar1 * SS + s * 16 + aq1 * 8);
        const int row = t >> 3, q = t & 7;
        cp16(smem_u32(&Vs[buf][row][q * 4]),
             Vb + (size_t)(s * 16 + row) * DEPTH + q * 8);
        CP_COMMIT();
    };

    issue(0);

    // Masked-column zero fill for this block's 128 rows (cols >= (tq+1)*128).
    // Warp-per-row-stride, lane-consecutive float4 -> fully coalesced STG;
    // overlaps with the cp.async prologue + first mma stages.
    {
        const int c40 = ((tq + 1) * 128) >> 2;     // first masked float4 col
        const float4 z4 = make_float4(0.f, 0.f, 0.f, 0.f);
        for (int row = wid; row < 128; row += 4) {
            float4* dst = (float4*)(Ab + (size_t)row * SS);
            for (int c4 = c40 + lane; c4 < (SS >> 2); c4 += 32)
                dst[c4] = z4;
        }
    }
    __syncthreads();

    for (int s = 0; s < NST; s++) {
        if (s + 1 < NST) { issue(s + 1); CP_WAIT(1); }
        else             { CP_WAIT(0); }
        __syncthreads();

        const int buf = s & 1;

        {
            const float i0 = inv_s[ar0], i1 = inv_s[ar1];
            uint4 w0 = *(const uint4*)&As[buf][ar0][aq0 * 4];
            uint4 w1 = *(const uint4*)&As[buf][ar1][aq1 * 4];
            float* d0 = Ab + (size_t)ar0 * SS + s * 16 + aq0 * 8;
            float* d1 = Ab + (size_t)ar1 * SS + s * 16 + aq1 * 8;
            float2 f0 = __half22float2(*(const __half2*)&w0.x);
            float2 f1 = __half22float2(*(const __half2*)&w0.y);
            float2 f2 = __half22float2(*(const __half2*)&w0.z);
            float2 f3 = __half22float2(*(const __half2*)&w0.w);
            *(float4*)d0       = make_float4(f0.x * i0, f0.y * i0, f1.x * i0, f1.y * i0);
            *(float4*)(d0 + 4) = make_float4(f2.x * i0, f2.y * i0, f3.x * i0, f3.y * i0);
            f0 = __half22float2(*(const __half2*)&w1.x);
            f1 = __half22float2(*(const __half2*)&w1.y);
            f2 = __half22float2(*(const __half2*)&w1.z);
            f3 = __half22float2(*(const __half2*)&w1.w);
            *(float4*)d1       = make_float4(f0.x * i1, f0.y * i1, f1.x * i1, f1.y * i1);
            *(float4*)(d1 + 4) = make_float4(f2.x * i1, f2.y * i1, f3.x * i1, f3.y * i1);
        }

        const uint32_t ab = asbase + (uint32_t)buf * TBUF;
        uint32_t a[4][4], b[4][2];
#pragma unroll
        for (int i = 0; i < 4; i++)
            ldsm_x4(a[i][0], a[i][1], a[i][2], a[i][3],
                    ab + aoff + (uint32_t)(i * 16) * TROWB);
#pragma unroll
        for (int p = 0; p < 2; p++)
            ldsm_x4_trans(b[2 * p][0], b[2 * p][1], b[2 * p + 1][0], b[2 * p + 1][1],
                          vbase[buf] + voff[p]);
#pragma unroll
        for (int i = 0; i < 4; i++)
#pragma unroll
            for (int j = 0; j < 4; j++)
                mma_f16(acc[i][j], a[i], b[j]);
        __syncthreads();
    }

#pragma unroll
    for (int i = 0; i < 4; i++) {
        const float iv0 = inv_s[wm + i * 16 + g];
        const float iv1 = inv_s[wm + i * 16 + g + 8];
#pragma unroll
        for (int j = 0; j < 4; j++) {
            const int c = wn + j * 8 + 2 * tg;
#pragma unroll
            for (int half = 0; half < 2; half++) {
                const float iv = half ? iv1 : iv0;
                const int q = tq * 128 + wm + i * 16 + g + half * 8;
                *(uint32_t*)&ctx[((size_t)bb * SS + q) * DD + h * DEPTH + c] =
                    h2pack(acc[i][j][half * 2 + 0] * iv, acc[i][j][half * 2 + 1] * iv);
            }
        }
    }
}

// ---------------------------------------------------------------------------
extern "C" void kernel_launch(void* const* d_in, const int* in_sizes, int n_in,
                              void* d_out, int out_size)
{
    const float* q    = (const float*)d_in[0];
    const float* k    = (const float*)d_in[1];
    const float* v    = (const float*)d_in[2];
    // d_in[3] = mask (causal; applied analytically)
    const float* wq   = (const float*)d_in[4];
    const float* bq   = (const float*)d_in[5];
    const float* wk   = (const float*)d_in[6];
    const float* bk   = (const float*)d_in[7];
    const float* wv   = (const float*)d_in[8];
    const float* bv   = (const float*)d_in[9];
    const float* wo   = (const float*)d_in[10];
    const float* bo   = (const float*)d_in[11];
    float* out = (float*)d_out;

    float *gattn, *gps;
    uint16_t *gqh, *gkh, *gvh, *gctxh, *gxh, *gwh, *geh;
    cudaGetSymbolAddress((void**)&gqh,  g_qh);
    cudaGetSymbolAddress((void**)&gkh,  g_kh);
    cudaGetSymbolAddress((void**)&gvh,  g_vh);
    cudaGetSymbolAddress((void**)&gctxh, g_ctxh);
    cudaGetSymbolAddress((void**)&gxh,  g_xh);
    cudaGetSymbolAddress((void**)&gwh,  g_wh);
    cudaGetSymbolAddress((void**)&geh,  g_eh);
    cudaGetSymbolAddress((void**)&gattn, g_attn_fb);
    cudaGetSymbolAddress((void**)&gps,  g_psum);

    static int attr_done = 0;
    if (!attr_done) {
        cudaFuncSetAttribute(proj_qkv, cudaFuncAttributeMaxDynamicSharedMemorySize, 49152);
        cudaFuncSetAttribute(proj_out, cudaFuncAttributeMaxDynamicSharedMemorySize, 49152);
        attr_done = 1;
    }

    const long long OUT_E = (long long)BB * SS * DD;
    const long long ATT_E = (long long)BB * HH * SS * SS;
    float* attn = ((long long)out_size >= OUT_E + ATT_E) ? (out + OUT_E) : gattn;

    const int NIN4 = MTOT * DD / 4;
    const int NW4  = DD * DD / 4;

    to_half_x<<<dim3(1024, 3), 256>>>((const float4*)q, (const float4*)k,
                                      (const float4*)v, gxh, NIN4);
    to_half_w<<<dim3(512, 4), 256>>>((const float4*)wq, (const float4*)wk,
                                     (const float4*)wv, (const float4*)wo, gwh, NW4);

    proj_qkv<<<dim3(DD / 128, MTOT / 128, 3), 128, 49152>>>(
        gxh, gwh, bq, bk, bv, gqh, gkh, gvh);

    attn_logits_exp<<<dim3(SS / 128, SS / 128, BB * HH), 256>>>(gqh, gkh, geh, gps);
    attn_ctx_f16<<<dim3(SS / 128, BB * HH), 128>>>(geh, gvh, gps, attn, gctxh);

    proj_out<<<dim3(DD / 128, MTOT / 128), 128, 49152>>>(
        gctxh, gwh + 3 * (size_t)DD * DD, bo, out);
}

// round 16
// speedup vs baseline: 1.0335x; 1.0335x over previous
#include <cuda_runtime.h>
#include <cuda_fp16.h>
#include <cstdint>

#define BB    4
#define SS    2048
#define DD    1024
#define HH    16
#define DEPTH 64
#define MTOT  (BB * SS)
#define NTK   (SS / 128)

#define MODE_OUT 0
#define MODE_KV  1
#define MODE_Q   2

__device__ uint16_t g_qh [(size_t)BB * HH * SS * DEPTH];
__device__ uint16_t g_kh [(size_t)BB * HH * SS * DEPTH];
__device__ uint16_t g_vh [(size_t)BB * HH * SS * DEPTH];
__device__ uint16_t g_ctxh[(size_t)MTOT * DD];
__device__ uint16_t g_xh [3][(size_t)MTOT * DD];
__device__ uint16_t g_wh [4][(size_t)DD * DD];
__device__ uint16_t g_eh [(size_t)BB * HH * SS * SS];   // fp16 exp scratch
__device__ float    g_attn_fb[(size_t)BB * HH * SS * SS];
__device__ float    g_psum[(size_t)BB * HH * SS * NTK];

// ---------------------------------------------------------------------------
__device__ __forceinline__ uint32_t h2pack(float lo, float hi) {
    __half2 h = __floats2half2_rn(lo, hi);
    return *reinterpret_cast<uint32_t*>(&h);
}

__device__ __forceinline__ void mma_f16(float* c, const uint32_t* a, const uint32_t* b) {
    asm volatile(
        "mma.sync.aligned.m16n8k16.row.col.f32.f16.f16.f32 "
        "{%0,%1,%2,%3}, {%4,%5,%6,%7}, {%8,%9}, {%0,%1,%2,%3};"
        : "+f"(c[0]), "+f"(c[1]), "+f"(c[2]), "+f"(c[3])
        : "r"(a[0]), "r"(a[1]), "r"(a[2]), "r"(a[3]), "r"(b[0]), "r"(b[1]));
}

__device__ __forceinline__ uint32_t smem_u32(const void* p) {
    return (uint32_t)__cvta_generic_to_shared(p);
}

__device__ __forceinline__ void cp16(uint32_t dst, const void* src) {
    asm volatile("cp.async.cg.shared.global [%0], [%1], 16;\n" :: "r"(dst), "l"(src));
}
#define CP_COMMIT() asm volatile("cp.async.commit_group;\n")
#define CP_WAIT(N)  asm volatile("cp.async.wait_group %0;\n" :: "n"(N))

__device__ __forceinline__ void ldsm_x4(uint32_t& r0, uint32_t& r1,
                                        uint32_t& r2, uint32_t& r3, uint32_t addr) {
    asm volatile("ldmatrix.sync.aligned.m8n8.x4.shared.b16 {%0,%1,%2,%3}, [%4];"
                 : "=r"(r0), "=r"(r1), "=r"(r2), "=r"(r3) : "r"(addr));
}

__device__ __forceinline__ void ldsm_x4_trans(uint32_t& r0, uint32_t& r1,
                                              uint32_t& r2, uint32_t& r3, uint32_t addr) {
    asm volatile("ldmatrix.sync.aligned.m8n8.x4.trans.shared.b16 {%0,%1,%2,%3}, [%4];"
                 : "=r"(r0), "=r"(r1), "=r"(r2), "=r"(r3) : "r"(addr));
}

#define TROW 12
#define TROWB (TROW * 4)
#define TBUF (128 * TROW * 4)

// ---------------------------------------------------------------------------
// fp32 -> fp16 conversion
// ---------------------------------------------------------------------------
__global__ __launch_bounds__(256) void to_half_x(
    const float4* __restrict__ q, const float4* __restrict__ k,
    const float4* __restrict__ v, uint16_t* __restrict__ outbase, int n4)
{
    const int z = blockIdx.y;
    const float4* in = (z == 0) ? q : (z == 1) ? k : v;
    uint2* out = (uint2*)(outbase + (size_t)z * MTOT * DD);
    int i = blockIdx.x * blockDim.x + threadIdx.x;
    const int stride = gridDim.x * blockDim.x;
    for (; i < n4; i += stride) {
        float4 w = in[i];
        out[i] = make_uint2(h2pack(w.x, w.y), h2pack(w.z, w.w));
    }
}

__global__ __launch_bounds__(256) void to_half_w(
    const float4* __restrict__ w0, const float4* __restrict__ w1,
    const float4* __restrict__ w2, const float4* __restrict__ w3,
    uint16_t* __restrict__ outbase, int n4)
{
    const int z = blockIdx.y;
    const float4* in = (z == 0) ? w0 : (z == 1) ? w1 : (z == 2) ? w2 : w3;
    uint2* out = (uint2*)(outbase + (size_t)z * DD * DD);
    int i = blockIdx.x * blockDim.x + threadIdx.x;
    const int stride = gridDim.x * blockDim.x;
    for (; i < n4; i += stride) {
        float4 w = in[i];
        out[i] = make_uint2(h2pack(w.x, w.y), h2pack(w.z, w.w));
    }
}

// ---------------------------------------------------------------------------
// Projection core: 128 thr, 128x128, warp 64x64, BK=16, 4-stage cp.async,
// ldmatrix fragments, single barrier per slab.
// ---------------------------------------------------------------------------
__device__ __forceinline__ void proj_body(
    const uint16_t* __restrict__ A, const uint16_t* __restrict__ W,
    const float* __restrict__ bias, void* __restrict__ Cout, int mode,
    uint32_t* dyn)
{
    uint32_t (*As)[128][TROW] = (uint32_t (*)[128][TROW])dyn;
    uint32_t (*Bs)[128][TROW] = (uint32_t (*)[128][TROW])(dyn + 4 * 128 * TROW);

    const int t   = threadIdx.x;
    const int m0  = blockIdx.y * 128;
    const int n0  = blockIdx.x * 128;
    const int wid = t >> 5, lane = t & 31;
    const int wm  = (wid >> 1) * 64;
    const int wn  = (wid & 1) * 64;
    const int g   = lane >> 2, tg = lane & 3;

    const uint16_t* Abase = A + (size_t)m0 * DD;
    const uint16_t* Wbase = W + (size_t)n0 * DD;

    const int lr = lane & 7;
    const uint32_t aoff = (uint32_t)(wm + ((lane >> 3) & 1) * 8 + lr) * TROWB
                        + ((lane >> 4) & 1) * 16;
    const uint32_t boff = (uint32_t)(wn + ((lane >> 4) & 1) * 8 + lr) * TROWB
                        + ((lane >> 3) & 1) * 16;
    const uint32_t asbase = smem_u32(&As[0][0][0]);
    const uint32_t bsbase = smem_u32(&Bs[0][0][0]);

    float acc[4][8][4];
#pragma unroll
    for (int i = 0; i < 4; i++)
#pragma unroll
        for (int j = 0; j < 8; j++)
#pragma unroll
            for (int r = 0; r < 4; r++) acc[i][j][r] = 0.f;

    const int NST = DD / 16;

    auto issue = [&](int p) {
        const int buf = p & 3;
#pragma unroll
        for (int u = 0; u < 2; u++) {
            const int slot = u * 128 + t;
            const int row  = slot >> 1;
            const int q    = slot & 1;
            cp16(smem_u32(&As[buf][row][q * 4]),
                 Abase + (size_t)row * DD + p * 16 + q * 8);
            cp16(smem_u32(&Bs[buf][row][q * 4]),
                 Wbase + (size_t)row * DD + p * 16 + q * 8);
        }
        CP_COMMIT();
    };

    issue(0); issue(1); issue(2);

    for (int s = 0; s < NST; s++) {
        if (s < NST - 2)      { CP_WAIT(2); }
        else if (s == NST - 2){ CP_WAIT(1); }
        else                  { CP_WAIT(0); }
        __syncthreads();
        if (s + 3 < NST) issue(s + 3);

        const int buf = s & 3;
        const uint32_t ab = asbase + (uint32_t)buf * TBUF;
        const uint32_t bb = bsbase + (uint32_t)buf * TBUF;
        uint32_t a[4][4], b[8][2];
#pragma unroll
        for (int i = 0; i < 4; i++)
            ldsm_x4(a[i][0], a[i][1], a[i][2], a[i][3],
                    ab + aoff + (uint32_t)(i * 16) * TROWB);
#pragma unroll
        for (int jj = 0; jj < 4; jj++)
            ldsm_x4(b[2 * jj][0], b[2 * jj][1], b[2 * jj + 1][0], b[2 * jj + 1][1],
                    bb + boff + (uint32_t)(jj * 16) * TROWB);
#pragma unroll
        for (int i = 0; i < 4; i++)
#pragma unroll
            for (int j = 0; j < 8; j++)
                mma_f16(acc[i][j], a[i], b[j]);
    }

#pragma unroll
    for (int i = 0; i < 4; i++) {
#pragma unroll
        for (int j = 0; j < 8; j++) {
            const int n = n0 + wn + j * 8 + 2 * tg;
#pragma unroll
            for (int half = 0; half < 2; half++) {
                const int m = m0 + wm + i * 16 + g + half * 8;
                float v0 = acc[i][j][half * 2 + 0] + bias[n];
                float v1 = acc[i][j][half * 2 + 1] + bias[n + 1];
                if (mode == MODE_OUT) {
                    float* C = (float*)Cout;
                    C[(size_t)m * DD + n]     = v0;
                    C[(size_t)m * DD + n + 1] = v1;
                } else {
                    if (mode == MODE_Q) { v0 *= 0.125f; v1 *= 0.125f; }
                    uint16_t* C = (uint16_t*)Cout;
                    const int bb2 = m / SS, s_ = m % SS;
                    const int h0 = n / DEPTH, d0 = n % DEPTH;
                    *(uint32_t*)&C[(((size_t)(bb2 * HH + h0)) * SS + s_) * DEPTH + d0] =
                        h2pack(v0, v1);
                }
            }
        }
    }
}

__global__ __launch_bounds__(128, 2) void proj_qkv(
    const uint16_t* __restrict__ X, const uint16_t* __restrict__ Wh,
    const float* __restrict__ bq, const float* __restrict__ bk,
    const float* __restrict__ bv,
    uint16_t* __restrict__ Oq, uint16_t* __restrict__ Ok, uint16_t* __restrict__ Ov)
{
    extern __shared__ uint32_t dyn[];
    const int z = blockIdx.z;
    const uint16_t* A = X + (size_t)z * MTOT * DD;
    const uint16_t* W = Wh + (size_t)z * DD * DD;
    const float* bias = (z == 0) ? bq : (z == 1) ? bk : bv;
    uint16_t* O = (z == 0) ? Oq : (z == 1) ? Ok : Ov;
    proj_body(A, W, bias, O, (z == 0) ? MODE_Q : MODE_KV, dyn);
}

__global__ __launch_bounds__(128, 2) void proj_out(
    const uint16_t* __restrict__ A, const uint16_t* __restrict__ W,
    const float* __restrict__ bias, float* __restrict__ C)
{
    extern __shared__ uint32_t dyn[];
    proj_body(A, W, bias, C, MODE_OUT, dyn);
}

// ---------------------------------------------------------------------------
// logits: e = (k<=q) ? exp(Q.K) : 0, fp16 scratch + psums. Masked blocks exit
// immediately; each strictly-lower block (tk<tq) zero-fills its MIRROR masked
// attn tile (tq'=tk, tk'=tq) — a 1:1 pairing covering all masked tiles —
// overlapped with its cp.async waits (logits has idle DRAM bandwidth).
// ---------------------------------------------------------------------------
__global__ __launch_bounds__(256) void attn_logits_exp(
    const uint16_t* __restrict__ Qh, const uint16_t* __restrict__ Kh,
    uint16_t* __restrict__ eh, float* __restrict__ attn, float* __restrict__ psum)
{
    const int bh = blockIdx.z;
    const int tq = blockIdx.y;
    const int tk = blockIdx.x;
    if (tk > tq) return;
    const int t  = threadIdx.x;

    const size_t abase = ((size_t)bh * SS + (size_t)tq * 128) * SS + (size_t)tk * 128;
    float* psrow = psum + ((size_t)bh * SS + (size_t)tq * 128) * NTK + tk;

    __shared__ uint32_t Qs[128][36];
    __shared__ uint32_t Ks[128][36];
    __shared__ float ps_s[128][5];

    const uint16_t* Qb = Qh + ((size_t)bh * SS + (size_t)tq * 128) * DEPTH;
    const uint16_t* Kb = Kh + ((size_t)bh * SS + (size_t)tk * 128) * DEPTH;

    const int wid = t >> 5, lane = t & 31;
    const int wm  = (wid >> 2) * 64;
    const int wn  = (wid & 3) * 32;
    const int g   = lane >> 2, tg = lane & 3;

#pragma unroll
    for (int u = 0; u < 4; u++) {
        const int slot = u * 256 + t;
        const int row  = slot >> 3;
        const int q    = slot & 7;
        cp16(smem_u32(&Qs[row][q * 4]), Qb + (size_t)row * DEPTH + q * 8);
        cp16(smem_u32(&Ks[row][q * 4]), Kb + (size_t)row * DEPTH + q * 8);
    }
    CP_COMMIT();

    // Mirror masked-tile zero fill (tk<tq): attn tile at rows tk*128, cols tq*128.
    // Overlaps with the cp.async in flight; 64KB coalesced STG.128.
    if (tk < tq) {
        const size_t mbase = ((size_t)bh * SS + (size_t)tk * 128) * SS + (size_t)tq * 128;
        float* mb = attn + mbase;
        const float4 z4 = make_float4(0.f, 0.f, 0.f, 0.f);
#pragma unroll
        for (int u = 0; u < 16; u++) {
            const int idx = u * 256 + t;
            const int row = idx >> 5, c4 = (idx & 31) * 4;
            *(float4*)&mb[(size_t)row * SS + c4] = z4;
        }
    }

    float acc[4][4][4];
#pragma unroll
    for (int i = 0; i < 4; i++)
#pragma unroll
        for (int j = 0; j < 4; j++)
#pragma unroll
            for (int r = 0; r < 4; r++) acc[i][j][r] = 0.f;

    CP_WAIT(0);
    __syncthreads();

#pragma unroll
    for (int s = 0; s < 4; s++) {
        const int w0 = s * 8;
        uint32_t a[4][4], b[4][2];
#pragma unroll
        for (int i = 0; i < 4; i++) {
            const int r = wm + i * 16;
            a[i][0] = Qs[r + g][w0 + tg];
            a[i][1] = Qs[r + g + 8][w0 + tg];
            a[i][2] = Qs[r + g][w0 + tg + 4];
            a[i][3] = Qs[r + g + 8][w0 + tg + 4];
        }
#pragma unroll
        for (int j = 0; j < 4; j++) {
            const int n = wn + j * 8;
            b[j][0] = Ks[n + g][w0 + tg];
            b[j][1] = Ks[n + g][w0 + tg + 4];
        }
#pragma unroll
        for (int i = 0; i < 4; i++)
#pragma unroll
            for (int j = 0; j < 4; j++)
                mma_f16(acc[i][j], a[i], b[j]);
    }

    const int qg0 = tq * 128, kg0 = tk * 128;
    float rowacc[4][2];
#pragma unroll
    for (int i = 0; i < 4; i++) { rowacc[i][0] = 0.f; rowacc[i][1] = 0.f; }

#pragma unroll
    for (int i = 0; i < 4; i++) {
#pragma unroll
        for (int j = 0; j < 4; j++) {
            const int kn = wn + j * 8 + 2 * tg;
#pragma unroll
            for (int half = 0; half < 2; half++) {
                const int qm = wm + i * 16 + g + half * 8;
                const int qg = qg0 + qm;
                const float v0 = (kg0 + kn     <= qg) ? __expf(acc[i][j][half * 2 + 0]) : 0.f;
                const float v1 = (kg0 + kn + 1 <= qg) ? __expf(acc[i][j][half * 2 + 1]) : 0.f;
                const uint32_t pair = h2pack(v0, v1);
                *(uint32_t*)&eh[abase + (size_t)qm * SS + kn] = pair;
                float2 fr = __half22float2(*(const __half2*)&pair);
                rowacc[i][half] += fr.x + fr.y;
            }
        }
    }
#pragma unroll
    for (int i = 0; i < 4; i++)
#pragma unroll
        for (int half = 0; half < 2; half++) {
            float v = rowacc[i][half];
            v += __shfl_xor_sync(0xffffffffu, v, 1);
            v += __shfl_xor_sync(0xffffffffu, v, 2);
            if (tg == 0) ps_s[wm + i * 16 + g + half * 8][wid & 3] = v;
        }
    __syncthreads();
    if (t < 128) {
        const float s4 = (ps_s[t][0] + ps_s[t][1]) + (ps_s[t][2] + ps_s[t][3]);
        psrow[(size_t)t * NTK] = s4;
    }
}

// ---------------------------------------------------------------------------
// ctx: acc = sum_k e·V, epilogue scale by inv; emits normalized fp32 attn.
// inv from the tq+1 valid psum entries. Longest-first schedule. No fill.
// ---------------------------------------------------------------------------
__global__ __launch_bounds__(128, 2) void attn_ctx_f16(
    const uint16_t* __restrict__ eh, const uint16_t* __restrict__ Vh,
    const float* __restrict__ psum, float* __restrict__ attn,
    uint16_t* __restrict__ ctx)
{
    const int tq = (NTK - 1) - blockIdx.x;
    const int bh = blockIdx.y;
    const int bb = bh / HH, h = bh % HH;
    const int t  = threadIdx.x;

    __shared__ uint32_t As[2][128][TROW];
    __shared__ uint32_t Vs[2][16][36];
    __shared__ float inv_s[128];

    const size_t qrow0 = (size_t)bh * SS + (size_t)tq * 128;
    const uint16_t* Eb = eh + qrow0 * SS;
    const uint16_t* Vb = Vh + (size_t)bh * SS * DEPTH;
    float* Ab = attn + qrow0 * SS;

    const int wid = t >> 5, lane = t & 31;
    const int wm  = (wid >> 1) * 64;
    const int wn  = (wid & 1) * 32;
    const int g   = lane >> 2, tg = lane & 3;

    const int lr = lane & 7;
    const uint32_t aoff = (uint32_t)(wm + ((lane >> 3) & 1) * 8 + lr) * TROWB
                        + ((lane >> 4) & 1) * 16;
    const uint32_t asbase = smem_u32(&As[0][0][0]);

    const uint32_t vbase[2] = { smem_u32(&Vs[0][0][0]), smem_u32(&Vs[1][0][0]) };
    uint32_t voff[2];
#pragma unroll
    for (int p = 0; p < 2; p++) {
        const int n0 = wn + p * 16 + (lane >> 4) * 8;
        voff[p] = (uint32_t)(((lane & 15) * 36 + (n0 >> 1)) * 4);
    }

    {
        const float* p0 = psum + (qrow0 + t) * NTK;
        float s0 = 0.f;
        for (int u = 0; u <= tq; u++) s0 += p0[u];
        inv_s[t] = 1.0f / s0;
    }

    float acc[4][4][4];
#pragma unroll
    for (int i = 0; i < 4; i++)
#pragma unroll
        for (int j = 0; j < 4; j++)
#pragma unroll
            for (int r = 0; r < 4; r++) acc[i][j][r] = 0.f;

    const int NST = (tq + 1) * 8;

    const int ar0 = t >> 1,          aq0 = (t & 1);
    const int ar1 = (t + 128) >> 1,  aq1 = ((t + 128) & 1);

    auto issue = [&](int s) {
        const int buf = s & 1;
        cp16(smem_u32(&As[buf][ar0][aq0 * 4]),
             Eb + (size_t)ar0 * SS + s * 16 + aq0 * 8);
        cp16(smem_u32(&As[buf][ar1][aq1 * 4]),
             Eb + (size_t)ar1 * SS + s * 16 + aq1 * 8);
        const int row = t >> 3, q = t & 7;
        cp16(smem_u32(&Vs[buf][row][q * 4]),
             Vb + (size_t)(s * 16 + row) * DEPTH + q * 8);
        CP_COMMIT();
    };

    issue(0);
    __syncthreads();

    for (int s = 0; s < NST; s++) {
        if (s + 1 < NST) { issue(s + 1); CP_WAIT(1); }
        else             { CP_WAIT(0); }
        __syncthreads();

        const int buf = s & 1;

        {
            const float i0 = inv_s[ar0], i1 = inv_s[ar1];
            uint4 w0 = *(const uint4*)&As[buf][ar0][aq0 * 4];
            uint4 w1 = *(const uint4*)&As[buf][ar1][aq1 * 4];
            float* d0 = Ab + (size_t)ar0 * SS + s * 16 + aq0 * 8;
            float* d1 = Ab + (size_t)ar1 * SS + s * 16 + aq1 * 8;
            float2 f0 = __half22float2(*(const __half2*)&w0.x);
            float2 f1 = __half22float2(*(const __half2*)&w0.y);
            float2 f2 = __half22float2(*(const __half2*)&w0.z);
            float2 f3 = __half22float2(*(const __half2*)&w0.w);
            *(float4*)d0       = make_float4(f0.x * i0, f0.y * i0, f1.x * i0, f1.y * i0);
            *(float4*)(d0 + 4) = make_float4(f2.x * i0, f2.y * i0, f3.x * i0, f3.y * i0);
            f0 = __half22float2(*(const __half2*)&w1.x);
            f1 = __half22float2(*(const __half2*)&w1.y);
            f2 = __half22float2(*(const __half2*)&w1.z);
            f3 = __half22float2(*(const __half2*)&w1.w);
            *(float4*)d1       = make_float4(f0.x * i1, f0.y * i1, f1.x * i1, f1.y * i1);
            *(float4*)(d1 + 4) = make_float4(f2.x * i1, f2.y * i1, f3.x * i1, f3.y * i1);
        }

        const uint32_t ab = asbase + (uint32_t)buf * TBUF;
        uint32_t a[4][4], b[4][2];
#pragma unroll
        for (int i = 0; i < 4; i++)
            ldsm_x4(a[i][0], a[i][1], a[i][2], a[i][3],
                    ab + aoff + (uint32_t)(i * 16) * TROWB);
#pragma unroll
        for (int p = 0; p < 2; p++)
            ldsm_x4_trans(b[2 * p][0], b[2 * p][1], b[2 * p + 1][0], b[2 * p + 1][1],
                          vbase[buf] + voff[p]);
#pragma unroll
        for (int i = 0; i < 4; i++)
#pragma unroll
            for (int j = 0; j < 4; j++)
                mma_f16(acc[i][j], a[i], b[j]);
        __syncthreads();
    }

#pragma unroll
    for (int i = 0; i < 4; i++) {
        const float iv0 = inv_s[wm + i * 16 + g];
        const float iv1 = inv_s[wm + i * 16 + g + 8];
#pragma unroll
        for (int j = 0; j < 4; j++) {
            const int c = wn + j * 8 + 2 * tg;
#pragma unroll
            for (int half = 0; half < 2; half++) {
                const float iv = half ? iv1 : iv0;
                const int q = tq * 128 + wm + i * 16 + g + half * 8;
                *(uint32_t*)&ctx[((size_t)bb * SS + q) * DD + h * DEPTH + c] =
                    h2pack(acc[i][j][half * 2 + 0] * iv, acc[i][j][half * 2 + 1] * iv);
            }
        }
    }
}

// ---------------------------------------------------------------------------
extern "C" void kernel_launch(void* const* d_in, const int* in_sizes, int n_in,
                              void* d_out, int out_size)
{
    const float* q    = (const float*)d_in[0];
    const float* k    = (const float*)d_in[1];
    const float* v    = (const float*)d_in[2];
    // d_in[3] = mask (causal; applied analytically)
    const float* wq   = (const float*)d_in[4];
    const float* bq   = (const float*)d_in[5];
    const float* wk   = (const float*)d_in[6];
    const float* bk   = (const float*)d_in[7];
    const float* wv   = (const float*)d_in[8];
    const float* bv   = (const float*)d_in[9];
    const float* wo   = (const float*)d_in[10];
    const float* bo   = (const float*)d_in[11];
    float* out = (float*)d_out;

    float *gattn, *gps;
    uint16_t *gqh, *gkh, *gvh, *gctxh, *gxh, *gwh, *geh;
    cudaGetSymbolAddress((void**)&gqh,  g_qh);
    cudaGetSymbolAddress((void**)&gkh,  g_kh);
    cudaGetSymbolAddress((void**)&gvh,  g_vh);
    cudaGetSymbolAddress((void**)&gctxh, g_ctxh);
    cudaGetSymbolAddress((void**)&gxh,  g_xh);
    cudaGetSymbolAddress((void**)&gwh,  g_wh);
    cudaGetSymbolAddress((void**)&geh,  g_eh);
    cudaGetSymbolAddress((void**)&gattn, g_attn_fb);
    cudaGetSymbolAddress((void**)&gps,  g_psum);

    static int attr_done = 0;
    if (!attr_done) {
        cudaFuncSetAttribute(proj_qkv, cudaFuncAttributeMaxDynamicSharedMemorySize, 49152);
        cudaFuncSetAttribute(proj_out, cudaFuncAttributeMaxDynamicSharedMemorySize, 49152);
        attr_done = 1;
    }

    const long long OUT_E = (long long)BB * SS * DD;
    const long long ATT_E = (long long)BB * HH * SS * SS;
    float* attn = ((long long)out_size >= OUT_E + ATT_E) ? (out + OUT_E) : gattn;

    const int NIN4 = MTOT * DD / 4;
    const int NW4  = DD * DD / 4;

    to_half_x<<<dim3(1024, 3), 256>>>((const float4*)q, (const float4*)k,
                                      (const float4*)v, gxh, NIN4);
    to_half_w<<<dim3(512, 4), 256>>>((const float4*)wq, (const float4*)wk,
                                     (const float4*)wv, (const float4*)wo, gwh, NW4);

    proj_qkv<<<dim3(DD / 128, MTOT / 128, 3), 128, 49152>>>(
        gxh, gwh, bq, bk, bv, gqh, gkh, gvh);

    attn_logits_exp<<<dim3(SS / 128, SS / 128, BB * HH), 256>>>(gqh, gkh, geh, attn, gps);
    attn_ctx_f16<<<dim3(SS / 128, BB * HH), 128>>>(geh, gvh, gps, attn, gctxh);

    proj_out<<<dim3(DD / 128, MTOT / 128), 128, 49152>>>(
        gctxh, gwh + 3 * (size_t)DD * DD, bo, out);
}